// round 2
// baseline (speedup 1.0000x reference)
#include <cuda_runtime.h>

#define N_NODES 50000
#define N_EDGES 1600000
#define DIM 128
#define NLAYERS 3
#define LN_EPS 1e-5f

// ---------------- scratch (static device globals; no allocation) ----------------
__device__ float g_deg[N_NODES];
__device__ float g_dinv[N_NODES];
__device__ int   g_cnt[N_NODES];
__device__ int   g_fill[N_NODES];
__device__ int   g_rowptr[N_NODES + 1];
__device__ int   g_csr_src[N_EDGES];
__device__ float g_csr_nrm[N_EDGES];
__device__ float g_xw[(size_t)N_NODES * DIM];
__device__ float g_hA[(size_t)N_NODES * DIM];
__device__ float g_hB[(size_t)N_NODES * DIM];

// ---------------- prep kernels ----------------
__global__ void k_init() {
    int i = blockIdx.x * blockDim.x + threadIdx.x;
    if (i < N_NODES) {
        g_deg[i] = 1.0f;   // self-loop weight
        g_cnt[i] = 0;
        g_fill[i] = 0;
    }
}

__global__ void k_edges(const int* __restrict__ row, const int* __restrict__ col,
                        const float* __restrict__ w) {
    int e = blockIdx.x * blockDim.x + threadIdx.x;
    if (e >= N_EDGES) return;
    int c = col[e];
    atomicAdd(&g_deg[c], w[e]);
    atomicAdd(&g_cnt[c], 1);
}

__global__ void k_dinv() {
    int i = blockIdx.x * blockDim.x + threadIdx.x;
    if (i < N_NODES) g_dinv[i] = rsqrtf(g_deg[i]);   // deg >= 1 always (self loop)
}

// single-block exclusive scan of g_cnt -> g_rowptr
__global__ void k_scan() {
    __shared__ int s[1024];
    int t = threadIdx.x;
    const int per = (N_NODES + 1023) / 1024;   // 49
    int lo = t * per;
    int hi = lo + per; if (hi > N_NODES) hi = N_NODES;
    int sum = 0;
    for (int i = lo; i < hi; i++) sum += g_cnt[i];
    s[t] = sum;
    __syncthreads();
    for (int off = 1; off < 1024; off <<= 1) {
        int v = (t >= off) ? s[t - off] : 0;
        __syncthreads();
        s[t] += v;
        __syncthreads();
    }
    int run = (t > 0) ? s[t - 1] : 0;
    for (int i = lo; i < hi; i++) {
        g_rowptr[i] = run;
        run += g_cnt[i];
    }
    if (t == 0) g_rowptr[N_NODES] = N_EDGES;
}

__global__ void k_fill(const int* __restrict__ row, const int* __restrict__ col,
                       const float* __restrict__ w) {
    int e = blockIdx.x * blockDim.x + threadIdx.x;
    if (e >= N_EDGES) return;
    int c = col[e];
    int r = row[e];
    int p = g_rowptr[c] + atomicAdd(&g_fill[c], 1);
    g_csr_src[p] = r;
    g_csr_nrm[p] = g_dinv[r] * w[e] * g_dinv[c];
}

// ---------------- GEMM: out[r][c] = sum_k h[r][k] * W[c][k] ----------------
// 64 rows x 128 cols per block, 256 threads, K-chunks of 32.
#define GR 64
__global__ void k_gemm(const float* __restrict__ h, const float* __restrict__ W,
                       float* __restrict__ out) {
    __shared__ float hs[GR][33];
    __shared__ float ws[32][132];   // stride 132 -> 16B-aligned float4 rows, conflict-free LDS.128
    int t  = threadIdx.x;
    int tx = t & 31;     // col group: cols tx*4 .. tx*4+3
    int ty = t >> 5;     // rows ty, ty+8, ..., ty+56
    int row0 = blockIdx.x * GR;

    float4 acc[8];
#pragma unroll
    for (int j = 0; j < 8; j++) acc[j] = make_float4(0.f, 0.f, 0.f, 0.f);

    for (int k0 = 0; k0 < DIM; k0 += 32) {
        // load h tile 64x32
#pragma unroll
        for (int i = 0; i < 8; i++) {
            int e = t + i * 256;
            int r = e >> 5, kk = e & 31;
            int gr = row0 + r;
            hs[r][kk] = (gr < N_NODES) ? h[(size_t)gr * DIM + k0 + kk] : 0.f;
        }
        // load W tile 128x32 (transposed into ws[kk][c])
#pragma unroll
        for (int i = 0; i < 16; i++) {
            int e = t + i * 256;
            int c = e >> 5, kk = e & 31;
            ws[kk][c] = W[(size_t)c * DIM + k0 + kk];
        }
        __syncthreads();
#pragma unroll
        for (int kk = 0; kk < 32; kk++) {
            float4 wv = *(const float4*)&ws[kk][tx * 4];
#pragma unroll
            for (int j = 0; j < 8; j++) {
                float hv = hs[ty + j * 8][kk];
                acc[j].x += hv * wv.x;
                acc[j].y += hv * wv.y;
                acc[j].z += hv * wv.z;
                acc[j].w += hv * wv.w;
            }
        }
        __syncthreads();
    }
#pragma unroll
    for (int j = 0; j < 8; j++) {
        int r = row0 + ty + j * 8;
        if (r < N_NODES)
            *(float4*)&out[(size_t)r * DIM + tx * 4] = acc[j];
    }
}

// ---------------- fused aggregate + bias + LN + (relu) + residual ----------------
// one warp per node; 4 features per lane
__global__ void k_node(const float* __restrict__ hin,     // identity (layer input)
                       const float* __restrict__ bias,
                       const float* __restrict__ gamma,
                       const float* __restrict__ beta,
                       float* __restrict__ hout,
                       int do_relu) {
    int gw = (blockIdx.x * blockDim.x + threadIdx.x) >> 5;
    int lane = threadIdx.x & 31;
    if (gw >= N_NODES) return;
    int node = gw;
    size_t fo = (size_t)lane * 4;

    float di = g_dinv[node];
    float4 acc = *(const float4*)&g_xw[(size_t)node * DIM + fo];
    float sl = di * di;
    acc.x *= sl; acc.y *= sl; acc.z *= sl; acc.w *= sl;

    int beg = g_rowptr[node], end = g_rowptr[node + 1];
    float4 acc2 = make_float4(0.f, 0.f, 0.f, 0.f);
    int j = beg;
    for (; j + 1 < end; j += 2) {
        int s0 = __ldg(&g_csr_src[j]);
        int s1 = __ldg(&g_csr_src[j + 1]);
        float n0 = __ldg(&g_csr_nrm[j]);
        float n1 = __ldg(&g_csr_nrm[j + 1]);
        float4 v0 = *(const float4*)&g_xw[(size_t)s0 * DIM + fo];
        float4 v1 = *(const float4*)&g_xw[(size_t)s1 * DIM + fo];
        acc.x  += v0.x * n0; acc.y  += v0.y * n0; acc.z  += v0.z * n0; acc.w  += v0.w * n0;
        acc2.x += v1.x * n1; acc2.y += v1.y * n1; acc2.z += v1.z * n1; acc2.w += v1.w * n1;
    }
    if (j < end) {
        int s0 = __ldg(&g_csr_src[j]);
        float n0 = __ldg(&g_csr_nrm[j]);
        float4 v0 = *(const float4*)&g_xw[(size_t)s0 * DIM + fo];
        acc.x += v0.x * n0; acc.y += v0.y * n0; acc.z += v0.z * n0; acc.w += v0.w * n0;
    }
    acc.x += acc2.x; acc.y += acc2.y; acc.z += acc2.z; acc.w += acc2.w;

    float4 b = *(const float4*)&bias[fo];
    acc.x += b.x; acc.y += b.y; acc.z += b.z; acc.w += b.w;

    // LayerNorm over 128 features spread across the warp
    float s = acc.x + acc.y + acc.z + acc.w;
#pragma unroll
    for (int o = 16; o; o >>= 1) s += __shfl_xor_sync(0xffffffffu, s, o);
    float mu = s * (1.0f / DIM);
    float dx0 = acc.x - mu, dx1 = acc.y - mu, dx2 = acc.z - mu, dx3 = acc.w - mu;
    float sq = dx0 * dx0 + dx1 * dx1 + dx2 * dx2 + dx3 * dx3;
#pragma unroll
    for (int o = 16; o; o >>= 1) sq += __shfl_xor_sync(0xffffffffu, sq, o);
    float rs = rsqrtf(sq * (1.0f / DIM) + LN_EPS);

    float4 g = *(const float4*)&gamma[fo];
    float4 bt = *(const float4*)&beta[fo];
    float4 y;
    y.x = dx0 * rs * g.x + bt.x;
    y.y = dx1 * rs * g.y + bt.y;
    y.z = dx2 * rs * g.z + bt.z;
    y.w = dx3 * rs * g.w + bt.w;
    if (do_relu) {
        y.x = fmaxf(y.x, 0.f); y.y = fmaxf(y.y, 0.f);
        y.z = fmaxf(y.z, 0.f); y.w = fmaxf(y.w, 0.f);
    }
    float4 id = *(const float4*)&hin[(size_t)node * DIM + fo];
    y.x += id.x; y.y += id.y; y.z += id.z; y.w += id.w;
    *(float4*)&hout[(size_t)node * DIM + fo] = y;
}

// ---------------- launch ----------------
extern "C" void kernel_launch(void* const* d_in, const int* in_sizes, int n_in,
                              void* d_out, int out_size) {
    const float* x  = (const float*)d_in[0];
    const int*   ei = (const int*)d_in[1];
    const float* ew = (const float*)d_in[2];
    const float* Ws = (const float*)d_in[3];
    const float* bs = (const float*)d_in[4];
    const float* gm = (const float*)d_in[5];
    const float* bt = (const float*)d_in[6];
    const int* row = ei;
    const int* col = ei + N_EDGES;

    float* hA; cudaGetSymbolAddress((void**)&hA, g_hA);
    float* hB; cudaGetSymbolAddress((void**)&hB, g_hB);
    float* xw; cudaGetSymbolAddress((void**)&xw, g_xw);
    (void)xw;

    int nb_nodes = (N_NODES + 255) / 256;
    int nb_edges = (N_EDGES + 255) / 256;

    k_init<<<nb_nodes, 256>>>();
    k_edges<<<nb_edges, 256>>>(row, col, ew);
    k_dinv<<<nb_nodes, 256>>>();
    k_scan<<<1, 1024>>>();
    k_fill<<<nb_edges, 256>>>(row, col, ew);

    const float* hin = x;
    float* houts[NLAYERS] = { hA, hB, (float*)d_out };
    int nb_gemm = (N_NODES + GR - 1) / GR;
    int nb_node = (N_NODES + 7) / 8;   // 8 warps/block

    for (int i = 0; i < NLAYERS; i++) {
        k_gemm<<<nb_gemm, 256>>>(hin, Ws + (size_t)i * DIM * DIM, xw);
        k_node<<<nb_node, 256>>>(hin, bs + (size_t)i * DIM, gm + (size_t)i * DIM,
                                 bt + (size_t)i * DIM, houts[i], (i < NLAYERS - 1) ? 1 : 0);
        hin = houts[i];
    }
}

// round 3
// speedup vs baseline: 1.1321x; 1.1321x over previous
#include <cuda_runtime.h>
#include <cuda_fp16.h>

#define N_NODES 50000
#define N_EDGES 1600000
#define DIM 128
#define NLAYERS 3
#define LN_EPS 1e-5f
#define NBLK 196   // ceil(N_NODES/256)

// ---------------- scratch (static device globals; no allocation) ----------------
__device__ float g_deg[N_NODES];
__device__ float g_dinv[N_NODES];
__device__ int   g_cnt[N_NODES];
__device__ int   g_fill[N_NODES];
__device__ int   g_bsum[NBLK];
__device__ int   g_boff[NBLK];
__device__ int   g_rowptr[N_NODES + 1];
__device__ int   g_csr_src[N_EDGES];
__device__ float g_csr_nrm[N_EDGES];
__device__ __half g_xw[(size_t)N_NODES * DIM];   // fp16 message buffer (halves gather traffic)
__device__ float g_hA[(size_t)N_NODES * DIM];
__device__ float g_hB[(size_t)N_NODES * DIM];

// ---------------- prep kernels ----------------
__global__ void k_init() {
    int i = blockIdx.x * blockDim.x + threadIdx.x;
    if (i < N_NODES) {
        g_deg[i] = 1.0f;   // self-loop weight
        g_cnt[i] = 0;
        g_fill[i] = 0;
    }
}

__global__ void k_edges(const int* __restrict__ row, const int* __restrict__ col,
                        const float* __restrict__ w) {
    int e = blockIdx.x * blockDim.x + threadIdx.x;
    if (e >= N_EDGES) return;
    int c = col[e];
    atomicAdd(&g_deg[c], w[e]);
    atomicAdd(&g_cnt[c], 1);
}

// 256-thread block exclusive scan (warp shuffles + 8 warp sums)
__device__ __forceinline__ int block_excl_scan256(int v) {
    int lane = threadIdx.x & 31;
    int w = threadIdx.x >> 5;
    int inc = v;
#pragma unroll
    for (int o = 1; o < 32; o <<= 1) {
        int n = __shfl_up_sync(0xffffffffu, inc, o);
        if (lane >= o) inc += n;
    }
    __shared__ int wsum[8];
    if (lane == 31) wsum[w] = inc;
    __syncthreads();
    if (w == 0) {
        int s = (lane < 8) ? wsum[lane] : 0;
#pragma unroll
        for (int o = 1; o < 8; o <<= 1) {
            int n = __shfl_up_sync(0xffffffffu, s, o);
            if (lane >= o) s += n;
        }
        if (lane < 8) wsum[lane] = s;   // inclusive warp sums
    }
    __syncthreads();
    int base = (w > 0) ? wsum[w - 1] : 0;
    return base + inc - v;   // exclusive prefix
}

__global__ void k_bsum() {
    int i = blockIdx.x * 256 + threadIdx.x;
    int v = (i < N_NODES) ? g_cnt[i] : 0;
    int ex = block_excl_scan256(v);
    if (threadIdx.x == 255) g_bsum[blockIdx.x] = ex + v;
}

__global__ void k_bscan() {
    int t = threadIdx.x;
    int v = (t < NBLK) ? g_bsum[t] : 0;
    int ex = block_excl_scan256(v);
    if (t < NBLK) g_boff[t] = ex;
    if (t == 0) g_rowptr[N_NODES] = N_EDGES;
}

__global__ void k_rowptr_dinv() {
    int i = blockIdx.x * 256 + threadIdx.x;
    int v = (i < N_NODES) ? g_cnt[i] : 0;
    int ex = block_excl_scan256(v);
    if (i < N_NODES) {
        g_rowptr[i] = g_boff[blockIdx.x] + ex;
        g_dinv[i] = rsqrtf(g_deg[i]);   // deg >= 1 always (self loop)
    }
}

__global__ void k_fill(const int* __restrict__ row, const int* __restrict__ col,
                       const float* __restrict__ w) {
    int e = blockIdx.x * blockDim.x + threadIdx.x;
    if (e >= N_EDGES) return;
    int c = col[e];
    int r = row[e];
    int p = g_rowptr[c] + atomicAdd(&g_fill[c], 1);
    g_csr_src[p] = r;
    g_csr_nrm[p] = g_dinv[r] * w[e] * g_dinv[c];
}

// ---------------- GEMM: out[r][c] = sum_k h[r][k] * W[c][k], fp32 acc -> fp16 store ----------------
#define GR 64
__global__ void k_gemm(const float* __restrict__ h, const float* __restrict__ W,
                       __half* __restrict__ out) {
    __shared__ float hs[GR][33];
    __shared__ float ws[32][132];   // stride 132 -> 16B-aligned float4 rows, conflict-free LDS.128
    int t  = threadIdx.x;
    int tx = t & 31;     // col group: cols tx*4 .. tx*4+3
    int ty = t >> 5;     // rows ty, ty+8, ..., ty+56
    int row0 = blockIdx.x * GR;

    float4 acc[8];
#pragma unroll
    for (int j = 0; j < 8; j++) acc[j] = make_float4(0.f, 0.f, 0.f, 0.f);

    for (int k0 = 0; k0 < DIM; k0 += 32) {
#pragma unroll
        for (int i = 0; i < 8; i++) {
            int e = t + i * 256;
            int r = e >> 5, kk = e & 31;
            int gr = row0 + r;
            hs[r][kk] = (gr < N_NODES) ? h[(size_t)gr * DIM + k0 + kk] : 0.f;
        }
#pragma unroll
        for (int i = 0; i < 16; i++) {
            int e = t + i * 256;
            int c = e >> 5, kk = e & 31;
            ws[kk][c] = W[(size_t)c * DIM + k0 + kk];
        }
        __syncthreads();
#pragma unroll
        for (int kk = 0; kk < 32; kk++) {
            float4 wv = *(const float4*)&ws[kk][tx * 4];
#pragma unroll
            for (int j = 0; j < 8; j++) {
                float hv = hs[ty + j * 8][kk];
                acc[j].x += hv * wv.x;
                acc[j].y += hv * wv.y;
                acc[j].z += hv * wv.z;
                acc[j].w += hv * wv.w;
            }
        }
        __syncthreads();
    }
#pragma unroll
    for (int j = 0; j < 8; j++) {
        int r = row0 + ty + j * 8;
        if (r < N_NODES) {
            __half2 h0 = __floats2half2_rn(acc[j].x, acc[j].y);
            __half2 h1 = __floats2half2_rn(acc[j].z, acc[j].w);
            uint2 u;
            u.x = *reinterpret_cast<unsigned*>(&h0);
            u.y = *reinterpret_cast<unsigned*>(&h1);
            *(uint2*)&out[(size_t)r * DIM + tx * 4] = u;
        }
    }
}

// ---------------- fused aggregate + bias + LN + (relu) + residual ----------------
// one warp per node; 4 features per lane; fp16 gathers, fp32 accumulation
__device__ __forceinline__ void acc_src(float4& a, int s, float n, int lane) {
    uint2 raw = __ldg((const uint2*)&g_xw[(size_t)s * DIM + lane * 4]);
    __half2 p0 = *reinterpret_cast<__half2*>(&raw.x);
    __half2 p1 = *reinterpret_cast<__half2*>(&raw.y);
    float2 f0 = __half22float2(p0);
    float2 f1 = __half22float2(p1);
    a.x += f0.x * n; a.y += f0.y * n; a.z += f1.x * n; a.w += f1.y * n;
}

__global__ void k_node(const float* __restrict__ hin,     // identity (layer input)
                       const float* __restrict__ bias,
                       const float* __restrict__ gamma,
                       const float* __restrict__ beta,
                       float* __restrict__ hout,
                       int do_relu) {
    int gw = (blockIdx.x * blockDim.x + threadIdx.x) >> 5;
    int lane = threadIdx.x & 31;
    if (gw >= N_NODES) return;
    int node = gw;

    float di = g_dinv[node];
    float4 acc = make_float4(0.f, 0.f, 0.f, 0.f);
    acc_src(acc, node, di * di, lane);   // self loop

    int beg = g_rowptr[node], end = g_rowptr[node + 1];
    float4 a1 = make_float4(0.f, 0.f, 0.f, 0.f);
    float4 a2 = make_float4(0.f, 0.f, 0.f, 0.f);
    float4 a3 = make_float4(0.f, 0.f, 0.f, 0.f);
    int j = beg;
    for (; j + 3 < end; j += 4) {
        int s0 = __ldg(&g_csr_src[j]);
        int s1 = __ldg(&g_csr_src[j + 1]);
        int s2 = __ldg(&g_csr_src[j + 2]);
        int s3 = __ldg(&g_csr_src[j + 3]);
        float n0 = __ldg(&g_csr_nrm[j]);
        float n1 = __ldg(&g_csr_nrm[j + 1]);
        float n2 = __ldg(&g_csr_nrm[j + 2]);
        float n3 = __ldg(&g_csr_nrm[j + 3]);
        acc_src(acc, s0, n0, lane);
        acc_src(a1,  s1, n1, lane);
        acc_src(a2,  s2, n2, lane);
        acc_src(a3,  s3, n3, lane);
    }
    for (; j < end; j++) {
        acc_src(acc, __ldg(&g_csr_src[j]), __ldg(&g_csr_nrm[j]), lane);
    }
    acc.x += a1.x + a2.x + a3.x;
    acc.y += a1.y + a2.y + a3.y;
    acc.z += a1.z + a2.z + a3.z;
    acc.w += a1.w + a2.w + a3.w;

    size_t fo = (size_t)lane * 4;
    float4 b = *(const float4*)&bias[fo];
    acc.x += b.x; acc.y += b.y; acc.z += b.z; acc.w += b.w;

    // LayerNorm over 128 features spread across the warp
    float s = acc.x + acc.y + acc.z + acc.w;
#pragma unroll
    for (int o = 16; o; o >>= 1) s += __shfl_xor_sync(0xffffffffu, s, o);
    float mu = s * (1.0f / DIM);
    float dx0 = acc.x - mu, dx1 = acc.y - mu, dx2 = acc.z - mu, dx3 = acc.w - mu;
    float sq = dx0 * dx0 + dx1 * dx1 + dx2 * dx2 + dx3 * dx3;
#pragma unroll
    for (int o = 16; o; o >>= 1) sq += __shfl_xor_sync(0xffffffffu, sq, o);
    float rs = rsqrtf(sq * (1.0f / DIM) + LN_EPS);

    float4 g = *(const float4*)&gamma[fo];
    float4 bt = *(const float4*)&beta[fo];
    float4 y;
    y.x = dx0 * rs * g.x + bt.x;
    y.y = dx1 * rs * g.y + bt.y;
    y.z = dx2 * rs * g.z + bt.z;
    y.w = dx3 * rs * g.w + bt.w;
    if (do_relu) {
        y.x = fmaxf(y.x, 0.f); y.y = fmaxf(y.y, 0.f);
        y.z = fmaxf(y.z, 0.f); y.w = fmaxf(y.w, 0.f);
    }
    float4 id = *(const float4*)&hin[(size_t)node * DIM + fo];
    y.x += id.x; y.y += id.y; y.z += id.z; y.w += id.w;
    *(float4*)&hout[(size_t)node * DIM + fo] = y;
}

// ---------------- launch ----------------
extern "C" void kernel_launch(void* const* d_in, const int* in_sizes, int n_in,
                              void* d_out, int out_size) {
    const float* x  = (const float*)d_in[0];
    const int*   ei = (const int*)d_in[1];
    const float* ew = (const float*)d_in[2];
    const float* Ws = (const float*)d_in[3];
    const float* bs = (const float*)d_in[4];
    const float* gm = (const float*)d_in[5];
    const float* bt = (const float*)d_in[6];
    const int* row = ei;
    const int* col = ei + N_EDGES;

    float*  hA; cudaGetSymbolAddress((void**)&hA, g_hA);
    float*  hB; cudaGetSymbolAddress((void**)&hB, g_hB);
    __half* xw; cudaGetSymbolAddress((void**)&xw, g_xw);

    int nb_nodes = (N_NODES + 255) / 256;
    int nb_edges = (N_EDGES + 255) / 256;

    k_init<<<nb_nodes, 256>>>();
    k_edges<<<nb_edges, 256>>>(row, col, ew);
    k_bsum<<<NBLK, 256>>>();
    k_bscan<<<1, 256>>>();
    k_rowptr_dinv<<<NBLK, 256>>>();
    k_fill<<<nb_edges, 256>>>(row, col, ew);

    const float* hin = x;
    float* houts[NLAYERS] = { hA, hB, (float*)d_out };
    int nb_gemm = (N_NODES + GR - 1) / GR;
    int nb_node = (N_NODES + 7) / 8;   // 8 warps/block

    for (int i = 0; i < NLAYERS; i++) {
        k_gemm<<<nb_gemm, 256>>>(hin, Ws + (size_t)i * DIM * DIM, xw);
        k_node<<<nb_node, 256>>>(hin, bs + (size_t)i * DIM, gm + (size_t)i * DIM,
                                 bt + (size_t)i * DIM, houts[i], (i < NLAYERS - 1) ? 1 : 0);
        hin = houts[i];
    }
}

// round 5
// speedup vs baseline: 1.6079x; 1.4203x over previous
#include <cuda_runtime.h>
#include <cuda_fp16.h>
#include <mma.h>

using namespace nvcuda;

#define N_NODES 50000
#define N_EDGES 1600000
#define DIM 128
#define NLAYERS 3
#define LN_EPS 1e-5f
#define NBLK 196   // ceil(N_NODES/256)

// ---------------- scratch (static device globals; no allocation) ----------------
__device__ float  g_deg[N_NODES];
__device__ float  g_dinv[N_NODES];
__device__ int    g_cnt[N_NODES];
__device__ int    g_fill[N_NODES];
__device__ int    g_bsum[NBLK];
__device__ int    g_boff[NBLK];
__device__ int    g_rowptr[N_NODES + 1];
__device__ int    g_csr_src[N_EDGES];
__device__ float  g_csr_nrm[N_EDGES];
__device__ __half g_xw[(size_t)N_NODES * DIM];       // fp16 message buffer
__device__ __half g_wh[(size_t)NLAYERS * DIM * DIM]; // fp16 weights
__device__ float  g_hA[(size_t)N_NODES * DIM];
__device__ float  g_hB[(size_t)N_NODES * DIM];

// ---------------- prep kernels ----------------
__global__ void k_init() {
    int i = blockIdx.x * blockDim.x + threadIdx.x;
    if (i < N_NODES) {
        g_deg[i] = 1.0f;   // self-loop weight
        g_cnt[i] = 0;
        g_fill[i] = 0;
    }
}

__global__ void k_wconv(const float* __restrict__ Ws) {
    int i = blockIdx.x * blockDim.x + threadIdx.x;
    if (i < NLAYERS * DIM * DIM) g_wh[i] = __float2half_rn(Ws[i]);
}

__global__ void k_edges(const int* __restrict__ row, const int* __restrict__ col,
                        const float* __restrict__ w) {
    int e = blockIdx.x * blockDim.x + threadIdx.x;
    if (e >= N_EDGES) return;
    int c = col[e];
    atomicAdd(&g_deg[c], w[e]);
    atomicAdd(&g_cnt[c], 1);
}

// 256-thread block exclusive scan (warp shuffles + 8 warp sums)
__device__ __forceinline__ int block_excl_scan256(int v) {
    int lane = threadIdx.x & 31;
    int w = threadIdx.x >> 5;
    int inc = v;
#pragma unroll
    for (int o = 1; o < 32; o <<= 1) {
        int n = __shfl_up_sync(0xffffffffu, inc, o);
        if (lane >= o) inc += n;
    }
    __shared__ int wsum[8];
    if (lane == 31) wsum[w] = inc;
    __syncthreads();
    if (w == 0) {
        int s = (lane < 8) ? wsum[lane] : 0;
#pragma unroll
        for (int o = 1; o < 8; o <<= 1) {
            int n = __shfl_up_sync(0xffffffffu, s, o);
            if (lane >= o) s += n;
        }
        if (lane < 8) wsum[lane] = s;   // inclusive warp sums
    }
    __syncthreads();
    int base = (w > 0) ? wsum[w - 1] : 0;
    return base + inc - v;   // exclusive prefix
}

__global__ void k_bsum() {
    int i = blockIdx.x * 256 + threadIdx.x;
    int v = (i < N_NODES) ? g_cnt[i] : 0;
    int ex = block_excl_scan256(v);
    if (threadIdx.x == 255) g_bsum[blockIdx.x] = ex + v;
    if (i < N_NODES) g_dinv[i] = rsqrtf(g_deg[i]);   // deg >= 1 (self loop)
}

__global__ void k_bscan() {
    int t = threadIdx.x;
    int v = (t < NBLK) ? g_bsum[t] : 0;
    int ex = block_excl_scan256(v);
    if (t < NBLK) g_boff[t] = ex;
    if (t == 0) g_rowptr[N_NODES] = N_EDGES;
}

__global__ void k_rowptr() {
    int i = blockIdx.x * 256 + threadIdx.x;
    int v = (i < N_NODES) ? g_cnt[i] : 0;
    int ex = block_excl_scan256(v);
    if (i < N_NODES) g_rowptr[i] = g_boff[blockIdx.x] + ex;
}

__global__ void k_fill(const int* __restrict__ row, const int* __restrict__ col,
                       const float* __restrict__ w) {
    int e = blockIdx.x * blockDim.x + threadIdx.x;
    if (e >= N_EDGES) return;
    int c = col[e];
    int r = row[e];
    int p = g_rowptr[c] + atomicAdd(&g_fill[c], 1);
    g_csr_src[p] = r;
    g_csr_nrm[p] = g_dinv[r] * w[e] * g_dinv[c];
}

// ---------------- tensor-core GEMM: out[r][c] = sum_k h[r][k] * W[c][k] ----------------
// 128x128 block tile, K=128 fully resident. 8 warps: 4(row) x 2(col), each 32x64.
#define GEMM_ROWS 128
#define APAD 136                       // 128 + 8 halves padding
#define SMEM_A_BYTES (128 * APAD * 2)
#define SMEM_B_BYTES (128 * APAD * 2)
#define SMEM_STAGE_BYTES (8 * 256 * 4)
#define SMEM_GEMM (SMEM_A_BYTES + SMEM_B_BYTES + SMEM_STAGE_BYTES)

__global__ void k_gemm_mma(const float* __restrict__ h, const __half* __restrict__ Wh,
                           __half* __restrict__ out) {
    extern __shared__ char smem[];
    __half* As = (__half*)smem;                           // [128][APAD]
    __half* Bs = (__half*)(smem + SMEM_A_BYTES);          // [128][APAD]  Bs[c][k] = W[c][k]
    float*  stage = (float*)(smem + SMEM_A_BYTES + SMEM_B_BYTES);

    int t = threadIdx.x;
    int warp = t >> 5, lane = t & 31;
    int row0 = blockIdx.x * GEMM_ROWS;

    // load A tile: 128x128 fp32 -> fp16 smem (4096 float4)
#pragma unroll
    for (int i = 0; i < 16; i++) {
        int idx = t + i * 256;
        int r = idx >> 5;        // 32 float4 per row
        int c4 = idx & 31;
        int gr = row0 + r;
        float4 v = (gr < N_NODES) ? *(const float4*)&h[(size_t)gr * DIM + c4 * 4]
                                  : make_float4(0.f, 0.f, 0.f, 0.f);
        __half2 p0 = __floats2half2_rn(v.x, v.y);
        __half2 p1 = __floats2half2_rn(v.z, v.w);
        uint2 u;
        u.x = *reinterpret_cast<unsigned*>(&p0);
        u.y = *reinterpret_cast<unsigned*>(&p1);
        *(uint2*)&As[r * APAD + c4 * 4] = u;
    }
    // load B tile: 128x128 half (4096 uint2)
#pragma unroll
    for (int i = 0; i < 16; i++) {
        int idx = t + i * 256;
        int r = idx >> 5;
        int c4 = idx & 31;
        *(uint2*)&Bs[r * APAD + c4 * 4] = *(const uint2*)&Wh[(size_t)r * DIM + c4 * 4];
    }
    __syncthreads();

    int wr = warp & 3;    // row group: wr*32
    int wc = warp >> 2;   // col group: wc*64

    wmma::fragment<wmma::accumulator, 16, 16, 16, float> c[2][4];
#pragma unroll
    for (int i = 0; i < 2; i++)
#pragma unroll
        for (int j = 0; j < 4; j++) wmma::fill_fragment(c[i][j], 0.f);

#pragma unroll
    for (int k = 0; k < 8; k++) {
        wmma::fragment<wmma::matrix_a, 16, 16, 16, __half, wmma::row_major> a[2];
        wmma::fragment<wmma::matrix_b, 16, 16, 16, __half, wmma::col_major> b[4];
#pragma unroll
        for (int i = 0; i < 2; i++)
            wmma::load_matrix_sync(a[i], As + (wr * 32 + i * 16) * APAD + k * 16, APAD);
#pragma unroll
        for (int j = 0; j < 4; j++)
            wmma::load_matrix_sync(b[j], Bs + (wc * 64 + j * 16) * APAD + k * 16, APAD);
#pragma unroll
        for (int i = 0; i < 2; i++)
#pragma unroll
            for (int j = 0; j < 4; j++)
                wmma::mma_sync(c[i][j], a[i], b[j], c[i][j]);
    }

    // epilogue: stage fp32 per-warp, convert to fp16, store
    float* st = stage + warp * 256;
#pragma unroll
    for (int i = 0; i < 2; i++) {
#pragma unroll
        for (int j = 0; j < 4; j++) {
            wmma::store_matrix_sync(st, c[i][j], 16, wmma::mem_row_major);
            __syncwarp();
            int r = lane >> 1;
            int c0 = (lane & 1) * 8;
            float4 v0 = *(float4*)&st[r * 16 + c0];
            float4 v1 = *(float4*)&st[r * 16 + c0 + 4];
            __half2 h0 = __floats2half2_rn(v0.x, v0.y);
            __half2 h1 = __floats2half2_rn(v0.z, v0.w);
            __half2 h2 = __floats2half2_rn(v1.x, v1.y);
            __half2 h3 = __floats2half2_rn(v1.z, v1.w);
            uint4 u;
            u.x = *reinterpret_cast<unsigned*>(&h0);
            u.y = *reinterpret_cast<unsigned*>(&h1);
            u.z = *reinterpret_cast<unsigned*>(&h2);
            u.w = *reinterpret_cast<unsigned*>(&h3);
            int grow = row0 + wr * 32 + i * 16 + r;
            if (grow < N_NODES)
                *(uint4*)&out[(size_t)grow * DIM + wc * 64 + j * 16 + c0] = u;
            __syncwarp();
        }
    }
}

// ---------------- fused aggregate + bias + LN + (relu) + residual ----------------
__device__ __forceinline__ void acc_src(float4& a, int s, float n, int lane) {
    uint2 raw = __ldg((const uint2*)&g_xw[(size_t)s * DIM + lane * 4]);
    __half2 p0 = *reinterpret_cast<__half2*>(&raw.x);
    __half2 p1 = *reinterpret_cast<__half2*>(&raw.y);
    float2 f0 = __half22float2(p0);
    float2 f1 = __half22float2(p1);
    a.x += f0.x * n; a.y += f0.y * n; a.z += f1.x * n; a.w += f1.y * n;
}

__global__ void k_node(const float* __restrict__ hin,
                       const float* __restrict__ bias,
                       const float* __restrict__ gamma,
                       const float* __restrict__ beta,
                       float* __restrict__ hout,
                       int do_relu) {
    int gw = (blockIdx.x * blockDim.x + threadIdx.x) >> 5;
    int lane = threadIdx.x & 31;
    if (gw >= N_NODES) return;
    int node = gw;

    float di = g_dinv[node];
    float4 acc = make_float4(0.f, 0.f, 0.f, 0.f);
    acc_src(acc, node, di * di, lane);   // self loop

    int beg = g_rowptr[node], end = g_rowptr[node + 1];
    float4 a1 = make_float4(0.f, 0.f, 0.f, 0.f);
    float4 a2 = make_float4(0.f, 0.f, 0.f, 0.f);
    float4 a3 = make_float4(0.f, 0.f, 0.f, 0.f);
    int j = beg;
    for (; j + 3 < end; j += 4) {
        int s0 = __ldg(&g_csr_src[j]);
        int s1 = __ldg(&g_csr_src[j + 1]);
        int s2 = __ldg(&g_csr_src[j + 2]);
        int s3 = __ldg(&g_csr_src[j + 3]);
        float n0 = __ldg(&g_csr_nrm[j]);
        float n1 = __ldg(&g_csr_nrm[j + 1]);
        float n2 = __ldg(&g_csr_nrm[j + 2]);
        float n3 = __ldg(&g_csr_nrm[j + 3]);
        acc_src(acc, s0, n0, lane);
        acc_src(a1,  s1, n1, lane);
        acc_src(a2,  s2, n2, lane);
        acc_src(a3,  s3, n3, lane);
    }
    for (; j < end; j++) {
        acc_src(acc, __ldg(&g_csr_src[j]), __ldg(&g_csr_nrm[j]), lane);
    }
    acc.x += a1.x + a2.x + a3.x;
    acc.y += a1.y + a2.y + a3.y;
    acc.z += a1.z + a2.z + a3.z;
    acc.w += a1.w + a2.w + a3.w;

    size_t fo = (size_t)lane * 4;
    float4 b = *(const float4*)&bias[fo];
    acc.x += b.x; acc.y += b.y; acc.z += b.z; acc.w += b.w;

    float s = acc.x + acc.y + acc.z + acc.w;
#pragma unroll
    for (int o = 16; o; o >>= 1) s += __shfl_xor_sync(0xffffffffu, s, o);
    float mu = s * (1.0f / DIM);
    float dx0 = acc.x - mu, dx1 = acc.y - mu, dx2 = acc.z - mu, dx3 = acc.w - mu;
    float sq = dx0 * dx0 + dx1 * dx1 + dx2 * dx2 + dx3 * dx3;
#pragma unroll
    for (int o = 16; o; o >>= 1) sq += __shfl_xor_sync(0xffffffffu, sq, o);
    float rs = rsqrtf(sq * (1.0f / DIM) + LN_EPS);

    float4 g = *(const float4*)&gamma[fo];
    float4 bt = *(const float4*)&beta[fo];
    float4 y;
    y.x = dx0 * rs * g.x + bt.x;
    y.y = dx1 * rs * g.y + bt.y;
    y.z = dx2 * rs * g.z + bt.z;
    y.w = dx3 * rs * g.w + bt.w;
    if (do_relu) {
        y.x = fmaxf(y.x, 0.f); y.y = fmaxf(y.y, 0.f);
        y.z = fmaxf(y.z, 0.f); y.w = fmaxf(y.w, 0.f);
    }
    float4 id = *(const float4*)&hin[(size_t)node * DIM + fo];
    y.x += id.x; y.y += id.y; y.z += id.z; y.w += id.w;
    *(float4*)&hout[(size_t)node * DIM + fo] = y;
}

// ---------------- launch ----------------
extern "C" void kernel_launch(void* const* d_in, const int* in_sizes, int n_in,
                              void* d_out, int out_size) {
    const float* x  = (const float*)d_in[0];
    const int*   ei = (const int*)d_in[1];
    const float* ew = (const float*)d_in[2];
    const float* Ws = (const float*)d_in[3];
    const float* bs = (const float*)d_in[4];
    const float* gm = (const float*)d_in[5];
    const float* bt = (const float*)d_in[6];
    const int* row = ei;
    const int* col = ei + N_EDGES;

    float*  hA; cudaGetSymbolAddress((void**)&hA, g_hA);
    float*  hB; cudaGetSymbolAddress((void**)&hB, g_hB);
    __half* xw; cudaGetSymbolAddress((void**)&xw, g_xw);
    __half* wh; cudaGetSymbolAddress((void**)&wh, g_wh);

    cudaFuncSetAttribute(k_gemm_mma, cudaFuncAttributeMaxDynamicSharedMemorySize, SMEM_GEMM);

    int nb_nodes = (N_NODES + 255) / 256;
    int nb_edges = (N_EDGES + 255) / 256;

    k_init<<<nb_nodes, 256>>>();
    k_wconv<<<(NLAYERS * DIM * DIM + 255) / 256, 256>>>(Ws);
    k_edges<<<nb_edges, 256>>>(row, col, ew);
    k_bsum<<<NBLK, 256>>>();
    k_bscan<<<1, 256>>>();
    k_rowptr<<<NBLK, 256>>>();
    k_fill<<<nb_edges, 256>>>(row, col, ew);

    const float* hin = x;
    float* houts[NLAYERS] = { hA, hB, (float*)d_out };
    int nb_gemm = (N_NODES + GEMM_ROWS - 1) / GEMM_ROWS;
    int nb_node = (N_NODES + 7) / 8;   // 8 warps/block

    for (int i = 0; i < NLAYERS; i++) {
        k_gemm_mma<<<nb_gemm, 256, SMEM_GEMM>>>(hin, wh + (size_t)i * DIM * DIM, xw);
        k_node<<<nb_node, 256>>>(hin, bs + (size_t)i * DIM, gm + (size_t)i * DIM,
                                 bt + (size_t)i * DIM, houts[i], (i < NLAYERS - 1) ? 1 : 0);
        hin = houts[i];
    }
}